// round 17
// baseline (speedup 1.0000x reference)
#include <cuda_runtime.h>
#include <cuda_fp16.h>
#include <cstdint>
#include <cstddef>

#define IN_F     4096
#define OUT_F    11008
#define M_TOKENS 4096

#define BM 128
#define BN 64
#define BK 128                     // per-iteration K depth (2 x 64 sub-blocks)
#define KITERS (IN_F / BK)         // 32

#define DQ_BLOCKS 44032     // 45,088,768 weight elems / 4 / 256
#define CX_BLOCKS 16384     // 16,777,216 x elems / 4 / 256

// -------- scratch (device globals: allocation-free) --------
__device__ __half g_W[(size_t)OUT_F * IN_F];    // dequantized weights fp16 [O, I]
__device__ __half g_X[(size_t)M_TOKENS * IN_F]; // activations fp16 [M, I]

// ---------------- PTX helpers (base-target features only) ----------------
__device__ __forceinline__ uint32_t smem_u32(const void* p) {
    uint32_t a;
    asm("{ .reg .u64 t; cvta.to.shared.u64 t, %1; cvt.u32.u64 %0, t; }" : "=r"(a) : "l"(p));
    return a;
}
__device__ __forceinline__ void cp16(uint32_t dst, const void* src) {
    asm volatile("cp.async.cg.shared.global [%0], [%1], 16;" :: "r"(dst), "l"(src) : "memory");
}
__device__ __forceinline__ void cp_commit() {
    asm volatile("cp.async.commit_group;" ::: "memory");
}
template <int N>
__device__ __forceinline__ void cp_wait() {
    asm volatile("cp.async.wait_group %0;" :: "n"(N) : "memory");
}
__device__ __forceinline__ void ldsm_x4(uint32_t& r0, uint32_t& r1, uint32_t& r2, uint32_t& r3,
                                        uint32_t addr) {
    asm volatile("ldmatrix.sync.aligned.m8n8.x4.shared.b16 {%0,%1,%2,%3}, [%4];"
                 : "=r"(r0), "=r"(r1), "=r"(r2), "=r"(r3) : "r"(addr));
}
__device__ __forceinline__ void mma16816(float* d, const uint32_t* a, const uint32_t* b) {
    asm volatile(
        "mma.sync.aligned.m16n8k16.row.col.f32.f16.f16.f32 "
        "{%0,%1,%2,%3}, {%4,%5,%6,%7}, {%8,%9}, {%0,%1,%2,%3};"
        : "+f"(d[0]), "+f"(d[1]), "+f"(d[2]), "+f"(d[3])
        : "r"(a[0]), "r"(a[1]), "r"(a[2]), "r"(a[3]), "r"(b[0]), "r"(b[1]));
}
__device__ __forceinline__ uint32_t sw128(uint32_t off) {
    return off ^ ((off >> 3) & 0x70);
}

// ---------------- fused prepass: dequant W + convert x (one launch) ----------------
__global__ void __launch_bounds__(256) prepass_kernel(const int* __restrict__ q,
                                                      const float* __restrict__ sc,
                                                      const int* __restrict__ mask,
                                                      const float* __restrict__ x) {
    if (blockIdx.x < DQ_BLOCKS) {
        size_t t = (size_t)blockIdx.x * 256 + threadIdx.x;   // 4 weight elements
        int4 qv = reinterpret_cast<const int4*>(q)[t];
        int4 mv = reinterpret_cast<const int4*>(mask)[t];
        float s = sc[(t * 4) >> 6];
        const float k = 2.0f / 7.0f;
        float w0 = mv.x ? 0.f : ((float)qv.x * k - 1.0f) * s;
        float w1 = mv.y ? 0.f : ((float)qv.y * k - 1.0f) * s;
        float w2 = mv.z ? 0.f : ((float)qv.z * k - 1.0f) * s;
        float w3 = mv.w ? 0.f : ((float)qv.w * k - 1.0f) * s;
        __half2 p0 = __floats2half2_rn(w0, w1);
        __half2 p1 = __floats2half2_rn(w2, w3);
        uint2 st;
        st.x = *reinterpret_cast<uint32_t*>(&p0);
        st.y = *reinterpret_cast<uint32_t*>(&p1);
        reinterpret_cast<uint2*>(g_W)[t] = st;
    } else {
        size_t t = (size_t)(blockIdx.x - DQ_BLOCKS) * 256 + threadIdx.x;  // 4 x elements
        float4 v = reinterpret_cast<const float4*>(x)[t];
        __half2 p0 = __floats2half2_rn(v.x, v.y);
        __half2 p1 = __floats2half2_rn(v.z, v.w);
        uint2 st;
        st.x = *reinterpret_cast<uint32_t*>(&p0);
        st.y = *reinterpret_cast<uint32_t*>(&p1);
        reinterpret_cast<uint2*>(g_X)[t] = st;
    }
}

// ---------------- GEMM: mma.sync fp16, BK=128 double-buffer, 128 thr, 2 CTA/SM ----------------
// Stage layout (48KB): A sub0 @0 (16KB), A sub1 @16K, B sub0 @32K (8KB), B sub1 @40K.
// Each sub-block is a standard 64-col (128B-row) SW128 tile -> existing algebra reused.
#define STAGE_BYTES 49152u
#define A_SUB 16384u
#define B_OFF 32768u
#define B_SUB 8192u
#define SMEM_TOTAL (2 * STAGE_BYTES)   // 96KB

__global__ void __launch_bounds__(128, 2) gemm_kernel(const float* __restrict__ bias,
                                                      float* __restrict__ out) {
    extern __shared__ __align__(1024) char smem[];
    uint32_t sb = smem_u32(smem);
    const int tid = threadIdx.x;
    const int lane = tid & 31;
    const int wid = tid >> 5;            // 4 warps: 2(M) x 2(N), warp tile 64x32
    const int wm = (wid & 1) * 64;
    const int wn = (wid >> 1) * 32;

    const int m_base = blockIdx.x * BM;  // fast-varying -> wave shares B in L2
    const int n_base = blockIdx.y * BN;

    // ---- producer per-thread invariants ----
    const int prow = tid >> 3;           // [0,16)
    const int pkc  = tid & 7;
    const __half* pA = g_X + (size_t)(m_base + prow) * IN_F + pkc * 8;
    const __half* pB = g_W + (size_t)(n_base + prow) * IN_F + pkc * 8;
    const uint32_t sA0 = sw128((uint32_t)(prow * 128 + pkc * 16));

    // ---- prologue: load stage 0 (K cols 0..127) ----
    {
        uint32_t a0 = sb + sA0;
        uint32_t b0 = sb + B_OFF + sA0;
#pragma unroll
        for (int i = 0; i < 16; ++i)     // A: rows prow+(i&7)*16, k-sub i>>3
            cp16(a0 + (uint32_t)(i >> 3) * A_SUB + (uint32_t)(i & 7) * 2048,
                 pA + (size_t)((i & 7) * 16) * IN_F + (i >> 3) * 64);
#pragma unroll
        for (int i = 0; i < 8; ++i)      // B: rows prow+(i&3)*16, k-sub i>>2
            cp16(b0 + (uint32_t)(i >> 2) * B_SUB + (uint32_t)(i & 3) * 2048,
                 pB + (size_t)((i & 3) * 16) * IN_F + (i >> 2) * 64);
        cp_commit();
    }

    float acc[4][4][4];
#pragma unroll
    for (int mi = 0; mi < 4; ++mi)
#pragma unroll
        for (int ni = 0; ni < 4; ++ni)
#pragma unroll
            for (int r = 0; r < 4; ++r) acc[mi][ni][r] = 0.0f;

    // ---- consumer ldsm invariants: sw(R,C) = R*128 + ((C ^ (R&7))*16) ----
    const int lrow = lane & 15;
    const int lcol = lane >> 4;
    uint32_t aRow[4], aXor[4], bRow[2], bXor[2];
#pragma unroll
    for (int mi = 0; mi < 4; ++mi) {
        int r = wm + mi * 16 + lrow;
        aRow[mi] = (uint32_t)(r * 128);
        aXor[mi] = (uint32_t)(r & 7);
    }
#pragma unroll
    for (int nj = 0; nj < 2; ++nj) {
        int r = wn + nj * 16 + lrow;
        bRow[nj] = (uint32_t)(r * 128);
        bXor[nj] = (uint32_t)(r & 7);
    }

    uint32_t soffR = 0;                  // read stage offset; write = soffR ^ STAGE_BYTES

    // ---- main loop: ONE wait+barrier per BK=128 (32 boundaries, was 64) ----
    for (int k = 0; k < KITERS; ++k) {
        cp_wait<0>();              // group committed at iter k-1 (or prologue) done
        __syncthreads();           // visibility + WAR on the stage being refilled

        const bool produce = (k + 1 < KITERS);
        const uint32_t aW = sb + (soffR ^ STAGE_BYTES) + sA0;
        const uint32_t bW = sb + (soffR ^ STAGE_BYTES) + B_OFF + sA0;
        const __half* nA = pA + (size_t)(k + 1) * BK;   // K base for next stage
        const __half* nB = pB + (size_t)(k + 1) * BK;

        const uint32_t aR = sb + soffR;
        const uint32_t bR = sb + soffR + B_OFF;

#pragma unroll
        for (int ks2 = 0; ks2 < 8; ++ks2) {          // 8 x k16 per BK=128
            const uint32_t subA = (uint32_t)(ks2 >> 2) * A_SUB;
            const uint32_t subB = (uint32_t)(ks2 >> 2) * B_SUB;
            const uint32_t cIdx = (uint32_t)((ks2 & 3) * 2 + lcol);
            uint32_t a[4][4];
            uint32_t b[4][2];
#pragma unroll
            for (int mi = 0; mi < 4; ++mi) {
                uint32_t addr = aR + subA + aRow[mi] + ((cIdx ^ aXor[mi]) << 4);
                ldsm_x4(a[mi][0], a[mi][1], a[mi][2], a[mi][3], addr);
            }
#pragma unroll
            for (int nj = 0; nj < 2; ++nj) {
                uint32_t addr = bR + subB + bRow[nj] + ((cIdx ^ bXor[nj]) << 4);
                uint32_t q0, q1, q2, q3;
                ldsm_x4(q0, q1, q2, q3, addr);
                b[2 * nj + 0][0] = q0; b[2 * nj + 0][1] = q2;
                b[2 * nj + 1][0] = q1; b[2 * nj + 1][1] = q3;
            }
            // Front-loaded producer: 6 cp16 in each of ks2 0..3 (A:4, B:2).
            // All copies issued by mid-iteration -> committed group lands well
            // before next iteration's wait<0>.
            if (produce && ks2 < 4) {
#pragma unroll
                for (int u = 0; u < 4; ++u) {        // A chunks i = ks2*4+u, i in [0,16)
                    int i = ks2 * 4 + u;
                    cp16(aW + (uint32_t)(i >> 3) * A_SUB + (uint32_t)(i & 7) * 2048,
                         nA + (size_t)((i & 7) * 16) * IN_F + (i >> 3) * 64);
                }
#pragma unroll
                for (int u = 0; u < 2; ++u) {        // B chunks i = ks2*2+u, i in [0,8)
                    int i = ks2 * 2 + u;
                    cp16(bW + (uint32_t)(i >> 2) * B_SUB + (uint32_t)(i & 3) * 2048,
                         nB + (size_t)((i & 3) * 16) * IN_F + (i >> 2) * 64);
                }
            }
#pragma unroll
            for (int mi = 0; mi < 4; ++mi)
#pragma unroll
                for (int ni = 0; ni < 4; ++ni)
                    mma16816(acc[mi][ni], a[mi], b[ni]);
        }

        cp_commit();               // one group per iteration (uniform accounting)
        soffR ^= STAGE_BYTES;
    }

    // ---- epilogue ----
    const int gid = lane >> 2;
    const int tq  = lane & 3;
    float2 bv[4];
#pragma unroll
    for (int ni = 0; ni < 4; ++ni) {
        int n = n_base + wn + ni * 8 + 2 * tq;
        bv[ni] = *reinterpret_cast<const float2*>(bias + n);
    }
#pragma unroll
    for (int mi = 0; mi < 4; ++mi) {
        int m0 = m_base + wm + mi * 16 + gid;
#pragma unroll
        for (int ni = 0; ni < 4; ++ni) {
            int n = n_base + wn + ni * 8 + 2 * tq;
            float2 v0 = make_float2(acc[mi][ni][0] + bv[ni].x, acc[mi][ni][1] + bv[ni].y);
            float2 v1 = make_float2(acc[mi][ni][2] + bv[ni].x, acc[mi][ni][3] + bv[ni].y);
            *reinterpret_cast<float2*>(out + (size_t)m0 * OUT_F + n) = v0;
            *reinterpret_cast<float2*>(out + (size_t)(m0 + 8) * OUT_F + n) = v1;
        }
    }
}

// ---------------- launch ----------------
extern "C" void kernel_launch(void* const* d_in, const int* in_sizes, int n_in,
                              void* d_out, int out_size) {
    const float* x    = (const float*)d_in[0];
    const int*   q    = (const int*)d_in[1];
    const float* sc   = (const float*)d_in[2];
    const int*   mask = (const int*)d_in[3];
    const float* bias = (const float*)d_in[4];
    float*       out  = (float*)d_out;

    prepass_kernel<<<DQ_BLOCKS + CX_BLOCKS, 256>>>(q, sc, mask, x);

    cudaFuncSetAttribute(gemm_kernel, cudaFuncAttributeMaxDynamicSharedMemorySize, SMEM_TOTAL);
    dim3 grid(M_TOKENS / BM, OUT_F / BN);             // (32, 172)
    gemm_kernel<<<grid, 128, SMEM_TOTAL>>>(bias, out);
}